// round 1
// baseline (speedup 1.0000x reference)
#include <cuda_runtime.h>
#include <math.h>

// ---------------------------------------------------------------------------
// FNet 2D FFT real part: x[8][4096][768] fp32 -> Re(FFT2 over (seq,hidden))
//
// Stage 1: FFT-768 along hidden per row (768 = 3 x 256, radix-4 DIF FFT256 x3
//          + radix-3 twiddle combine). Keep l = 0..384 (Hermitian symmetry of
//          real input), store complex to g_inter[b][s][388] (padded).
// Stage 2: FFT-4096 (radix-4 DIF, in smem) along seq, 4 adjacent l-columns per
//          block. Write Re directly for l<=384, mirrored for l=385..767.
// ---------------------------------------------------------------------------

__device__ float2 g_tw4096[4096];
__device__ float2 g_tw768[768];
__device__ float2 g_inter[8ll * 4096ll * 388ll];   // ~102 MB scratch

__device__ __forceinline__ float2 cmul(float2 a, float2 b) {
    return make_float2(fmaf(a.x, b.x, -a.y * b.y), fmaf(a.x, b.y, a.y * b.x));
}

__global__ void init_tw_kernel() {
    int i = blockIdx.x * blockDim.x + threadIdx.x;
    if (i < 4096) {
        double ang = -2.0 * 3.14159265358979323846 * (double)i / 4096.0;
        g_tw4096[i] = make_float2((float)cos(ang), (float)sin(ang));
    }
    if (i < 768) {
        double ang = -2.0 * 3.14159265358979323846 * (double)i / 768.0;
        g_tw768[i] = make_float2((float)cos(ang), (float)sin(ang));
    }
}

// ---------------------------------------------------------------------------
// Stage 1
// ---------------------------------------------------------------------------
#define S1_SUBSTRIDE 276   // 256 + 16 pad + 4 (bank-skew between subs)
#define S1_ROWS 4

__global__ __launch_bounds__(256) void stage1_kernel(const float* __restrict__ x) {
    extern __shared__ float2 sm[];
    float2* tw   = sm;            // 768 entries: W_768^t
    float2* subs = sm + 768;      // 3 * S1_SUBSTRIDE
    const int tid = threadIdx.x;

    for (int i = tid; i < 768; i += 256) tw[i] = g_tw768[i];

    const int row0 = blockIdx.x * S1_ROWS;
    for (int r = 0; r < S1_ROWS; r++) {
        const int row = row0 + r;                       // 0 .. 32767 = b*4096+s
        const float* xr = x + (long long)row * 768;
        __syncthreads();
        // scatter real input into 3 decimated subsequences (n = 3m + sub)
        #pragma unroll
        for (int it = 0; it < 3; it++) {
            int i = tid + it * 256;
            float v = xr[i];
            int sub = i % 3;
            int m = i / 3;
            subs[sub * S1_SUBSTRIDE + m + (m >> 4)] = make_float2(v, 0.0f);
        }
        // three FFT-256, radix-4 DIF, outputs digit-reversed
        #pragma unroll 1
        for (int qlog = 6; qlog >= 0; qlog -= 2) {
            __syncthreads();
            if (tid < 192) {
                const int sub = tid >> 6;
                const int bf  = tid & 63;
                float2* d = subs + sub * S1_SUBSTRIDE;
                const int Q = 1 << qlog;
                const int j = bf & (Q - 1);
                const int g = bf >> qlog;
                const int base = (g << (qlog + 2)) + j;
                const int i0 = base, i1 = base + Q, i2 = base + 2 * Q, i3 = base + 3 * Q;
                float2 a0 = d[i0 + (i0 >> 4)];
                float2 a1 = d[i1 + (i1 >> 4)];
                float2 a2 = d[i2 + (i2 >> 4)];
                float2 a3 = d[i3 + (i3 >> 4)];
                float2 t0 = make_float2(a0.x + a2.x, a0.y + a2.y);
                float2 t1 = make_float2(a0.x - a2.x, a0.y - a2.y);
                float2 t2 = make_float2(a1.x + a3.x, a1.y + a3.y);
                float2 t3 = make_float2(a1.x - a3.x, a1.y - a3.y);
                float2 z0 = make_float2(t0.x + t2.x, t0.y + t2.y);
                float2 z2 = make_float2(t0.x - t2.x, t0.y - t2.y);
                float2 z1 = make_float2(t1.x + t3.y, t1.y - t3.x);   // t1 - i t3
                float2 z3 = make_float2(t1.x - t3.y, t1.y + t3.x);   // t1 + i t3
                // W_256^{j*(64>>qlog)*v} = tw768[3*j*(64>>qlog)*v]
                const int tb = 3 * j * (64 >> qlog);
                d[i0 + (i0 >> 4)] = z0;
                d[i1 + (i1 >> 4)] = cmul(z1, tw[tb]);
                d[i2 + (i2 >> 4)] = cmul(z2, tw[2 * tb]);
                d[i3 + (i3 >> 4)] = cmul(z3, tw[3 * tb]);
            }
        }
        __syncthreads();
        // combine: X[k] = F0[rev(k%256)] + W_768^k F1[...] + W_768^{2k} F2[...]
        float2* outp = g_inter + (long long)row * 388;
        for (int k = tid; k < 388; k += 256) {
            float2 X;
            if (k <= 384) {
                int km = k & 255;
                int rk = ((km & 3) << 6) | (((km >> 2) & 3) << 4)
                       | (((km >> 4) & 3) << 2) | ((km >> 6) & 3);
                int pp = rk + (rk >> 4);
                float2 F0 = subs[pp];
                float2 F1 = subs[S1_SUBSTRIDE + pp];
                float2 F2 = subs[2 * S1_SUBSTRIDE + pp];
                int i2k = 2 * k; if (i2k >= 768) i2k -= 768;
                float2 c1 = cmul(tw[k], F1);
                float2 c2 = cmul(tw[i2k], F2);
                X = make_float2(F0.x + c1.x + c2.x, F0.y + c1.y + c2.y);
            } else {
                X = make_float2(0.0f, 0.0f);   // pad columns 385..387
            }
            outp[k] = X;
        }
    }
}

// ---------------------------------------------------------------------------
// Stage 2
// ---------------------------------------------------------------------------
#define S2_COLSTRIDE 4356                       // 4096+16 pad, +skew for banks
#define S2_SMEM_F2 (4096 + 4 * S2_COLSTRIDE)    // 21520 float2 = 172160 B

__global__ __launch_bounds__(512) void stage2_kernel(float* __restrict__ out) {
    extern __shared__ float2 sm[];
    float2* tw   = sm;            // 4096 entries: W_4096^t
    float2* data = sm + 4096;     // 4 columns
    const int tid  = threadIdx.x;
    const int b    = blockIdx.y;
    const int l0   = blockIdx.x * 4;

    for (int i = tid; i < 4096; i += 512) tw[i] = g_tw4096[i];

    // load 4 adjacent l-columns: each s contributes 32 contiguous bytes
    const float4* src = reinterpret_cast<const float4*>(
        g_inter + ((long long)b * 4096) * 388 + l0);
    #pragma unroll
    for (int it = 0; it < 16; it++) {
        int fid = tid + it * 512;          // 0..8191
        int s = fid >> 1, half = fid & 1;
        float4 v = src[(long long)s * 194 + half];
        int c = half * 2;
        int pp = s + (s >> 4);
        data[c * S2_COLSTRIDE + pp]       = make_float2(v.x, v.y);
        data[(c + 1) * S2_COLSTRIDE + pp] = make_float2(v.z, v.w);
    }

    // radix-4 DIF FFT-4096, 4 columns in parallel (128 threads each)
    const int col = tid >> 7;
    const int ct  = tid & 127;
    float2* d = data + col * S2_COLSTRIDE;

    #pragma unroll 1
    for (int qlog = 10; qlog >= 0; qlog -= 2) {
        __syncthreads();
        const int Q  = 1 << qlog;
        const int tf = 1024 >> qlog;
        #pragma unroll
        for (int u = 0; u < 8; u++) {
            const int bf = ct + u * 128;          // 0..1023
            const int j = bf & (Q - 1);
            const int g = bf >> qlog;
            const int base = (g << (qlog + 2)) + j;
            const int i0 = base, i1 = base + Q, i2 = base + 2 * Q, i3 = base + 3 * Q;
            float2 a0 = d[i0 + (i0 >> 4)];
            float2 a1 = d[i1 + (i1 >> 4)];
            float2 a2 = d[i2 + (i2 >> 4)];
            float2 a3 = d[i3 + (i3 >> 4)];
            float2 t0 = make_float2(a0.x + a2.x, a0.y + a2.y);
            float2 t1 = make_float2(a0.x - a2.x, a0.y - a2.y);
            float2 t2 = make_float2(a1.x + a3.x, a1.y + a3.y);
            float2 t3 = make_float2(a1.x - a3.x, a1.y - a3.y);
            float2 z0 = make_float2(t0.x + t2.x, t0.y + t2.y);
            float2 z2 = make_float2(t0.x - t2.x, t0.y - t2.y);
            float2 z1 = make_float2(t1.x + t3.y, t1.y - t3.x);
            float2 z3 = make_float2(t1.x - t3.y, t1.y + t3.x);
            const int t1i = j * tf;               // < 1024; 3*t1i < 4096
            d[i0 + (i0 >> 4)] = z0;
            d[i1 + (i1 >> 4)] = cmul(z1, tw[t1i]);
            d[i2 + (i2 >> 4)] = cmul(z2, tw[2 * t1i]);
            d[i3 + (i3 >> 4)] = cmul(z3, tw[3 * t1i]);
        }
    }
    __syncthreads();

    // write real parts: direct [k][l0..l0+3], mirror [4096-k][768-l]
    float* ob = out + (long long)b * 4096 * 768;
    const bool full = (l0 < 384);
    #pragma unroll
    for (int it = 0; it < 8; it++) {
        const int k = tid + it * 512;
        const int rk = ((k & 3) << 10) | (((k >> 2) & 3) << 8) | (((k >> 4) & 3) << 6)
                     | (((k >> 6) & 3) << 4) | (((k >> 8) & 3) << 2) | ((k >> 10) & 3);
        const int pp = rk + (rk >> 4);
        const float y0 = data[0 * S2_COLSTRIDE + pp].x;
        const float y1 = data[1 * S2_COLSTRIDE + pp].x;
        const float y2 = data[2 * S2_COLSTRIDE + pp].x;
        const float y3 = data[3 * S2_COLSTRIDE + pp].x;
        if (full) {
            *reinterpret_cast<float4*>(ob + (long long)k * 768 + l0) =
                make_float4(y0, y1, y2, y3);
            const int k2 = (4096 - k) & 4095;
            float* mb = ob + (long long)k2 * 768 + (768 - l0);
            mb[-1] = y1;                 // l' = 767 - l0
            mb[-2] = y2;                 // l' = 766 - l0
            mb[-3] = y3;                 // l' = 765 - l0
            if (l0 > 0) mb[0] = y0;      // l' = 768 - l0 (skip when l0 == 0)
        } else {
            ob[(long long)k * 768 + 384] = y0;   // Nyquist column, self-symmetric
        }
    }
}

// ---------------------------------------------------------------------------
extern "C" void kernel_launch(void* const* d_in, const int* in_sizes, int n_in,
                              void* d_out, int out_size) {
    const float* x = (const float*)d_in[0];
    float* out = (float*)d_out;
    (void)in_sizes; (void)n_in; (void)out_size;

    cudaFuncSetAttribute(stage2_kernel,
                         cudaFuncAttributeMaxDynamicSharedMemorySize,
                         S2_SMEM_F2 * (int)sizeof(float2));

    init_tw_kernel<<<16, 256>>>();
    stage1_kernel<<<8192, 256, (768 + 3 * S1_SUBSTRIDE) * sizeof(float2)>>>(x);
    stage2_kernel<<<dim3(97, 8), 512, S2_SMEM_F2 * sizeof(float2)>>>(out);
}

// round 2
// speedup vs baseline: 2.0762x; 2.0762x over previous
#include <cuda_runtime.h>

// ---------------------------------------------------------------------------
// FNet 2D FFT real part: x[8][4096][768] fp32 -> Re(FFT2 over (seq,hidden))
//
// Stage 1: FFT-768 along hidden per row (768 = 3 x 256, radix-4 DIF FFT256 x3
//          + radix-3 twiddle combine). One WARP per row, __syncwarp only.
//          Keep l = 0..384 (Hermitian symmetry), store to g_inter[row][388].
// Stage 2: FFT-4096 (radix-4 DIF in smem) along seq, 4 adjacent l-columns per
//          block, 1024 threads. Sequential smem readout (conflict-free), output
//          row = digit-reverse(j). Mirror writes cover l = 385..767.
// ---------------------------------------------------------------------------

__device__ __align__(16) float2 g_inter[8ll * 4096ll * 388ll];   // ~102 MB scratch

__device__ __forceinline__ float2 cmul(float2 a, float2 b) {
    return make_float2(fmaf(a.x, b.x, -a.y * b.y), fmaf(a.x, b.y, a.y * b.x));
}

// ---------------------------------------------------------------------------
// Stage 1: one warp per row, 8 rows per 256-thread block
// ---------------------------------------------------------------------------
#define S1_STRIDE 292            // 256 + 32 pad (i + (i>>3)) + 4 skew
#define S1_SMEM_F2 (768 + 8 * 3 * S1_STRIDE)   // 7776 float2 = 62208 B

__global__ __launch_bounds__(256) void stage1_kernel(const float* __restrict__ x) {
    extern __shared__ float2 sm[];
    float2* tw = sm;                       // 768 entries: W_768^t
    const int tid  = threadIdx.x;
    const int lane = tid & 31;
    const int wid  = tid >> 5;

    for (int i = tid; i < 768; i += 256) {
        float s, c;
        sincospif(-(float)i * (1.0f / 384.0f), &s, &c);   // e^{-2*pi*i*t/768}
        tw[i] = make_float2(c, s);
    }
    __syncthreads();

    float2* subs = sm + 768 + wid * 3 * S1_STRIDE;
    const int row = blockIdx.x * 8 + wid;             // 0..32767
    const float4* xr = reinterpret_cast<const float4*>(x + (long long)row * 768);

    // scatter real input into 3 decimated subsequences (n = 3m + sub)
    #pragma unroll
    for (int it = 0; it < 6; it++) {
        float4 v = xr[lane + 32 * it];
        int e = 4 * (lane + 32 * it);
        float vv[4] = {v.x, v.y, v.z, v.w};
        #pragma unroll
        for (int u = 0; u < 4; u++) {
            int ee = e + u;
            int sub = ee % 3, m = ee / 3;
            subs[sub * S1_STRIDE + m + (m >> 3)] = make_float2(vv[u], 0.0f);
        }
    }
    __syncwarp();

    // three FFT-256, radix-4 DIF; outputs digit-reversed
    #pragma unroll
    for (int qlog = 6; qlog >= 0; qlog -= 2) {
        #pragma unroll
        for (int it = 0; it < 6; it++) {
            const int bfg = lane + 32 * it;          // 0..191
            const int sub = bfg >> 6;
            const int bf  = bfg & 63;
            float2* d = subs + sub * S1_STRIDE;
            const int Q = 1 << qlog;
            const int j = bf & (Q - 1);
            const int g = bf >> qlog;
            const int base = (g << (qlog + 2)) + j;
            const int i0 = base, i1 = base + Q, i2 = base + 2 * Q, i3 = base + 3 * Q;
            float2 a0 = d[i0 + (i0 >> 3)];
            float2 a1 = d[i1 + (i1 >> 3)];
            float2 a2 = d[i2 + (i2 >> 3)];
            float2 a3 = d[i3 + (i3 >> 3)];
            float2 t0 = make_float2(a0.x + a2.x, a0.y + a2.y);
            float2 t1 = make_float2(a0.x - a2.x, a0.y - a2.y);
            float2 t2 = make_float2(a1.x + a3.x, a1.y + a3.y);
            float2 t3 = make_float2(a1.x - a3.x, a1.y - a3.y);
            float2 z0 = make_float2(t0.x + t2.x, t0.y + t2.y);
            float2 z2 = make_float2(t0.x - t2.x, t0.y - t2.y);
            float2 z1 = make_float2(t1.x + t3.y, t1.y - t3.x);   // t1 - i t3
            float2 z3 = make_float2(t1.x - t3.y, t1.y + t3.x);   // t1 + i t3
            const int tb = 3 * j * (64 >> qlog);     // W_256^{jv} = tw768[3jv]
            d[i0 + (i0 >> 3)] = z0;
            d[i1 + (i1 >> 3)] = cmul(z1, tw[tb]);
            d[i2 + (i2 >> 3)] = cmul(z2, tw[2 * tb]);
            d[i3 + (i3 >> 3)] = cmul(z3, tw[3 * tb]);
        }
        __syncwarp();
    }

    // combine: X[k] = F0[rev(k%256)] + W_768^k F1[...] + W_768^{2k} F2[...]
    float2* outp = g_inter + (long long)row * 388;
    #pragma unroll
    for (int it = 0; it < 13; it++) {
        const int k = lane + 32 * it;
        if (k < 388) {
            float2 X;
            if (k <= 384) {
                int km = k & 255;
                int rk = ((km & 3) << 6) | (((km >> 2) & 3) << 4)
                       | (((km >> 4) & 3) << 2) | ((km >> 6) & 3);
                int pp = rk + (rk >> 3);
                float2 F0 = subs[pp];
                float2 F1 = subs[S1_STRIDE + pp];
                float2 F2 = subs[2 * S1_STRIDE + pp];
                int i2k = 2 * k; if (i2k >= 768) i2k -= 768;
                float2 c1 = cmul(tw[k], F1);
                float2 c2 = cmul(tw[i2k], F2);
                X = make_float2(F0.x + c1.x + c2.x, F0.y + c1.y + c2.y);
            } else {
                X = make_float2(0.0f, 0.0f);    // pad columns 385..387
            }
            outp[k] = X;
        }
    }
}

// ---------------------------------------------------------------------------
// Stage 2: FFT-4096 along seq, 4 l-columns per block, 1024 threads
// ---------------------------------------------------------------------------
#define S2_STRIDE 4612                      // 4096 + 512 pad (i + (i>>3)) + 4 skew
#define S2_SMEM_F2 (1024 + 4 * S2_STRIDE)   // 19472 float2 = 155776 B

__global__ __launch_bounds__(1024) void stage2_kernel(float* __restrict__ out) {
    extern __shared__ float2 sm[];
    float2* tw   = sm;           // 1024 entries: W_4096^t, t < 1024
    float2* data = sm + 1024;
    const int tid = threadIdx.x;
    const int b   = blockIdx.y;
    const int l0  = blockIdx.x * 4;

    {
        float s, c;
        sincospif(-(float)tid * (1.0f / 2048.0f), &s, &c);   // e^{-2*pi*i*t/4096}
        tw[tid] = make_float2(c, s);
    }

    // load 4 adjacent l-columns: each s contributes 32 contiguous bytes
    const float4* src = reinterpret_cast<const float4*>(
        g_inter + ((long long)b * 4096) * 388 + l0);
    #pragma unroll
    for (int it = 0; it < 8; it++) {
        int fid = tid + it * 1024;           // 0..8191
        int s = fid >> 1, half = fid & 1;
        float4 v = src[(long long)s * 194 + half];
        int c = half * 2;
        int pp = s + (s >> 3);
        data[c * S2_STRIDE + pp]       = make_float2(v.x, v.y);
        data[(c + 1) * S2_STRIDE + pp] = make_float2(v.z, v.w);
    }
    __syncthreads();

    // radix-4 DIF FFT-4096, 4 columns in parallel (256 threads each)
    const int col = tid >> 8;
    const int ct  = tid & 255;
    float2* d = data + col * S2_STRIDE;

    #pragma unroll 1
    for (int qlog = 10; qlog >= 0; qlog -= 2) {
        const int Q  = 1 << qlog;
        const int tf = 1024 >> qlog;
        #pragma unroll
        for (int u = 0; u < 4; u++) {
            const int bf = ct + u * 256;             // 0..1023
            const int j = bf & (Q - 1);
            const int g = bf >> qlog;
            const int base = (g << (qlog + 2)) + j;
            const int i0 = base, i1 = base + Q, i2 = base + 2 * Q, i3 = base + 3 * Q;
            float2 a0 = d[i0 + (i0 >> 3)];
            float2 a1 = d[i1 + (i1 >> 3)];
            float2 a2 = d[i2 + (i2 >> 3)];
            float2 a3 = d[i3 + (i3 >> 3)];
            float2 t0 = make_float2(a0.x + a2.x, a0.y + a2.y);
            float2 t1 = make_float2(a0.x - a2.x, a0.y - a2.y);
            float2 t2 = make_float2(a1.x + a3.x, a1.y + a3.y);
            float2 t3 = make_float2(a1.x - a3.x, a1.y - a3.y);
            float2 z0 = make_float2(t0.x + t2.x, t0.y + t2.y);
            float2 z2 = make_float2(t0.x - t2.x, t0.y - t2.y);
            float2 z1 = make_float2(t1.x + t3.y, t1.y - t3.x);
            float2 z3 = make_float2(t1.x - t3.y, t1.y + t3.x);
            float2 w1 = tw[j * tf];                  // j*tf < 1024
            float2 w2 = cmul(w1, w1);
            float2 w3 = cmul(w2, w1);
            d[i0 + (i0 >> 3)] = z0;
            d[i1 + (i1 >> 3)] = cmul(z1, w1);
            d[i2 + (i2 >> 3)] = cmul(z2, w2);
            d[i3 + (i3 >> 3)] = cmul(z3, w3);
        }
        __syncthreads();
    }

    // readout: sequential smem (conflict-free), output row = rev(j).
    // direct [k][l0..l0+3]; mirror Re Y[(4096-k)%4096][768-l] = Re Y[k][l].
    float* ob = out + (long long)b * 4096 * 768;
    const bool full = (l0 < 384);
    #pragma unroll
    for (int it = 0; it < 4; it++) {
        const int jj = tid + it * 1024;              // 0..4095, sequential
        const int pp = jj + (jj >> 3);
        const float y0 = data[0 * S2_STRIDE + pp].x;
        const float y1 = data[1 * S2_STRIDE + pp].x;
        const float y2 = data[2 * S2_STRIDE + pp].x;
        const float y3 = data[3 * S2_STRIDE + pp].x;
        const int k = ((jj & 3) << 10) | (((jj >> 2) & 3) << 8) | (((jj >> 4) & 3) << 6)
                    | (((jj >> 6) & 3) << 4) | (((jj >> 8) & 3) << 2) | ((jj >> 10) & 3);
        if (full) {
            *reinterpret_cast<float4*>(ob + (long long)k * 768 + l0) =
                make_float4(y0, y1, y2, y3);
            const int k2 = (4096 - k) & 4095;
            float* mb = ob + (long long)k2 * 768 + (768 - l0);
            mb[-3] = y3;                                         // l' = 765 - l0
            *reinterpret_cast<float2*>(mb - 2) = make_float2(y2, y1);  // 766,767 - l0
            if (l0 > 0) mb[0] = y0;                              // l' = 768 - l0
        } else {
            ob[(long long)k * 768 + 384] = y0;   // Nyquist column, self-symmetric
        }
    }
}

// ---------------------------------------------------------------------------
extern "C" void kernel_launch(void* const* d_in, const int* in_sizes, int n_in,
                              void* d_out, int out_size) {
    const float* x = (const float*)d_in[0];
    float* out = (float*)d_out;
    (void)in_sizes; (void)n_in; (void)out_size;

    cudaFuncSetAttribute(stage1_kernel,
                         cudaFuncAttributeMaxDynamicSharedMemorySize,
                         S1_SMEM_F2 * (int)sizeof(float2));
    cudaFuncSetAttribute(stage2_kernel,
                         cudaFuncAttributeMaxDynamicSharedMemorySize,
                         S2_SMEM_F2 * (int)sizeof(float2));

    stage1_kernel<<<4096, 256, S1_SMEM_F2 * sizeof(float2)>>>(x);
    stage2_kernel<<<dim3(97, 8), 1024, S2_SMEM_F2 * sizeof(float2)>>>(out);
}